// round 1
// baseline (speedup 1.0000x reference)
#include <cuda_runtime.h>
#include <math.h>

#define NE 8
#define ND 1024
#define NH 2048
#define NO 1024
#define NB 4096
#define NSLOT (2*NB)

// ---- static device scratch (no allocations allowed) ----
static __device__ float g_Y1[(size_t)NSLOT * NH];   // 64 MB
static __device__ float g_Y2[(size_t)NSLOT * NH];   // 64 MB
static __device__ float g_Y3[(size_t)NSLOT * NO];   // 32 MB
static __device__ int   g_gidx[NB * 2];
static __device__ float g_gwt[NB * 2];
static __device__ int   g_slot[NB * 2];
static __device__ int   g_cnt[NE];
static __device__ int   g_off[NE];
static __device__ int   g_cur[NE];
static __device__ int   g_rowtok[NSLOT];

// ============================================================
// Gating: logits[b,e] = sum_j combined[b,j]*gw[j,e] + gb[e];
// top-2 + softmax, matching jax top_k tie-break (lowest index).
// ============================================================
__global__ void gate_kernel(const float* __restrict__ x0, const float* __restrict__ x1,
                            const float* __restrict__ x2, const float* __restrict__ x3,
                            const float* __restrict__ x4, const float* __restrict__ x5,
                            const float* __restrict__ x6, const float* __restrict__ x7,
                            const float* __restrict__ gw, const float* __restrict__ gb)
{
    int b   = blockIdx.x;
    int tid = threadIdx.x;
    const float* xs[NE] = {x0,x1,x2,x3,x4,x5,x6,x7};

    float acc[NE];
#pragma unroll
    for (int e = 0; e < NE; e++) acc[e] = 0.f;

#pragma unroll
    for (int ix = 0; ix < NE; ix++) {
        const float* xp = xs[ix] + (size_t)b * ND;
        for (int d = tid; d < ND; d += 256) {
            float v = xp[d];
            const float* g = gw + (size_t)(ix * ND + d) * NE;
#pragma unroll
            for (int e = 0; e < NE; e++) acc[e] += v * g[e];
        }
    }

    __shared__ float red[NE][256];
#pragma unroll
    for (int e = 0; e < NE; e++) red[e][tid] = acc[e];
    __syncthreads();
    for (int off = 128; off > 0; off >>= 1) {
        if (tid < off) {
#pragma unroll
            for (int e = 0; e < NE; e++) red[e][tid] += red[e][tid + off];
        }
        __syncthreads();
    }

    if (tid == 0) {
        float lg[NE];
#pragma unroll
        for (int e = 0; e < NE; e++) lg[e] = red[e][0] + gb[e];
        int i0 = 0;
#pragma unroll
        for (int e = 1; e < NE; e++) if (lg[e] > lg[i0]) i0 = e;
        int i1 = (i0 == 0) ? 1 : 0;
#pragma unroll
        for (int e = 0; e < NE; e++) if (e != i0 && lg[e] > lg[i1]) i1 = e;
        // stable softmax over {lg[i0] (max), lg[i1]}
        float ex = expf(lg[i1] - lg[i0]);
        float inv = 1.f / (1.f + ex);
        g_gidx[2*b]   = i0;  g_gidx[2*b+1] = i1;
        g_gwt[2*b]    = inv; g_gwt[2*b+1]  = ex * inv;
    }
}

// ============================================================
// Dispatch bookkeeping
// ============================================================
__global__ void init_cnt_kernel() {
    if (threadIdx.x < NE) g_cnt[threadIdx.x] = 0;
}

__global__ void count_kernel() {
    int b = blockIdx.x * blockDim.x + threadIdx.x;
    if (b < NB) {
        atomicAdd(&g_cnt[g_gidx[2*b]],   1);
        atomicAdd(&g_cnt[g_gidx[2*b+1]], 1);
    }
}

__global__ void offs_kernel() {
    if (threadIdx.x == 0) {
        int s = 0;
        for (int e = 0; e < NE; e++) { g_off[e] = s; g_cur[e] = s; s += g_cnt[e]; }
    }
}

__global__ void scatter_kernel() {
    int b = blockIdx.x * blockDim.x + threadIdx.x;
    if (b < NB) {
#pragma unroll
        for (int k = 0; k < 2; k++) {
            int e = g_gidx[2*b + k];
            int p = atomicAdd(&g_cur[e], 1);
            g_rowtok[p]   = b;
            g_slot[2*b+k] = p;
        }
    }
}

// ============================================================
// fp32 tiled GEMM over per-expert row segments.
// C[base+m, :] = act( A_rows[m, :K] @ W_e[K,N] + bias_e[N] )
// GATHER=1: A rows come from x_e via g_rowtok; else from Abase (Y buffers).
// BM=128, BN=64, BK=16, 256 threads, 8x4 microtile, reg-prefetch pipeline.
// ============================================================
template<int K, int N, int RELU, int GATHER>
__global__ __launch_bounds__(256)
void gemm_kernel(const float* __restrict__ Abase,
                 const float* __restrict__ x0, const float* __restrict__ x1,
                 const float* __restrict__ x2, const float* __restrict__ x3,
                 const float* __restrict__ x4, const float* __restrict__ x5,
                 const float* __restrict__ x6, const float* __restrict__ x7,
                 const float* __restrict__ Wg, const float* __restrict__ Bg,
                 float* __restrict__ C)
{
    const int BM = 128, BN = 64, BK = 16;
    int e    = blockIdx.z;
    int cnt  = g_cnt[e];
    int m0   = blockIdx.x * BM;
    if (m0 >= cnt) return;
    int base = g_off[e];
    int n0   = blockIdx.y * BN;
    const float* W    = Wg + (size_t)e * K * N;
    const float* bias = Bg + (size_t)e * N;

    // per-thread A row pointers (loader mapping: row = (tid>>4) + i*16)
    const float* Arow[8];
    {
        const float* Ae;
        if (GATHER) {
            const float* xsarr[NE] = {x0,x1,x2,x3,x4,x5,x6,x7};
            Ae = xsarr[e];
        } else {
            Ae = Abase;
        }
        int lm0 = threadIdx.x >> 4;
#pragma unroll
        for (int i = 0; i < 8; i++) {
            int m  = m0 + lm0 + i * 16;
            int mm = (m < cnt) ? m : 0;          // clamp: garbage rows never stored
            int grow;
            if (GATHER) grow = g_rowtok[base + mm];
            else        grow = base + mm;
            Arow[i] = Ae + (size_t)grow * K;
        }
    }
    int lk  = threadIdx.x & 15;   // A loader: k within tile
    int lkb = threadIdx.x >> 6;   // B loader: k base (0..3), rows lkb + i*4
    int lnb = threadIdx.x & 63;   // B loader: n within tile

    __shared__ __align__(16) float As[BK][BM + 4];
    __shared__ __align__(16) float Bs[BK][BN];

    int ty = threadIdx.x >> 4;    // compute rows ty*8 .. ty*8+7
    int tx = threadIdx.x & 15;    // compute cols tx*4 .. tx*4+3

    float acc[8][4];
#pragma unroll
    for (int i = 0; i < 8; i++)
#pragma unroll
        for (int j = 0; j < 4; j++) acc[i][j] = 0.f;

    // preload first K-tile into registers
    float ar[8], br[4];
#pragma unroll
    for (int i = 0; i < 8; i++) ar[i] = Arow[i][lk];
#pragma unroll
    for (int i = 0; i < 4; i++) br[i] = W[(size_t)(lkb + i*4) * N + n0 + lnb];

    int lm0 = threadIdx.x >> 4;
    for (int k0 = 0; k0 < K; k0 += BK) {
#pragma unroll
        for (int i = 0; i < 8; i++) As[lk][lm0 + i*16] = ar[i];
#pragma unroll
        for (int i = 0; i < 4; i++) Bs[lkb + i*4][lnb] = br[i];
        __syncthreads();

        if (k0 + BK < K) {
#pragma unroll
            for (int i = 0; i < 8; i++) ar[i] = Arow[i][k0 + BK + lk];
#pragma unroll
            for (int i = 0; i < 4; i++)
                br[i] = W[(size_t)(k0 + BK + lkb + i*4) * N + n0 + lnb];
        }

#pragma unroll
        for (int kk = 0; kk < BK; kk++) {
            float4 a0 = *(const float4*)&As[kk][ty * 8];
            float4 a1 = *(const float4*)&As[kk][ty * 8 + 4];
            float4 bv = *(const float4*)&Bs[kk][tx * 4];
            float av[8] = {a0.x, a0.y, a0.z, a0.w, a1.x, a1.y, a1.z, a1.w};
            float bb[4] = {bv.x, bv.y, bv.z, bv.w};
#pragma unroll
            for (int i = 0; i < 8; i++)
#pragma unroll
                for (int j = 0; j < 4; j++)
                    acc[i][j] = fmaf(av[i], bb[j], acc[i][j]);
        }
        __syncthreads();
    }

    // epilogue: bias (+ relu) + store
    float b0 = bias[n0 + tx*4 + 0];
    float b1 = bias[n0 + tx*4 + 1];
    float b2 = bias[n0 + tx*4 + 2];
    float b3 = bias[n0 + tx*4 + 3];
#pragma unroll
    for (int i = 0; i < 8; i++) {
        int m = m0 + ty * 8 + i;
        if (m < cnt) {
            float4 v;
            v.x = acc[i][0] + b0;
            v.y = acc[i][1] + b1;
            v.z = acc[i][2] + b2;
            v.w = acc[i][3] + b3;
            if (RELU) {
                v.x = fmaxf(v.x, 0.f); v.y = fmaxf(v.y, 0.f);
                v.z = fmaxf(v.z, 0.f); v.w = fmaxf(v.w, 0.f);
            }
            *(float4*)&C[(size_t)(base + m) * N + n0 + tx * 4] = v;
        }
    }
}

// ============================================================
// Combine: out[b,:] = w0 * Y3[slot0,:] + w1 * Y3[slot1,:]
// ============================================================
__global__ void combine_kernel(float* __restrict__ out, const float* __restrict__ Y3)
{
    int b = blockIdx.x;
    int o = blockIdx.y * 256 + threadIdx.x;
    int s0 = g_slot[2*b], s1 = g_slot[2*b+1];
    float w0 = g_gwt[2*b], w1 = g_gwt[2*b+1];
    out[(size_t)b * NO + o] = w0 * Y3[(size_t)s0 * NO + o]
                            + w1 * Y3[(size_t)s1 * NO + o];
}

// ============================================================
extern "C" void kernel_launch(void* const* d_in, const int* in_sizes, int n_in,
                              void* d_out, int out_size)
{
    const float* x[NE];
    for (int i = 0; i < NE; i++) x[i] = (const float*)d_in[i];
    const float* gw    = (const float*)d_in[8];
    const float* gb    = (const float*)d_in[9];
    const float* w_in  = (const float*)d_in[10];
    const float* b_in  = (const float*)d_in[11];
    const float* w_h   = (const float*)d_in[12];
    const float* b_h   = (const float*)d_in[13];
    const float* w_out = (const float*)d_in[14];
    const float* b_out = (const float*)d_in[15];
    float* out = (float*)d_out;

    float *pY1, *pY2, *pY3;
    cudaGetSymbolAddress((void**)&pY1, g_Y1);
    cudaGetSymbolAddress((void**)&pY2, g_Y2);
    cudaGetSymbolAddress((void**)&pY3, g_Y3);

    gate_kernel<<<NB, 256>>>(x[0],x[1],x[2],x[3],x[4],x[5],x[6],x[7], gw, gb);
    init_cnt_kernel<<<1, 32>>>();
    count_kernel<<<NB/256, 256>>>();
    offs_kernel<<<1, 32>>>();
    scatter_kernel<<<NB/256, 256>>>();

    dim3 g1(32, NH/64, NE);
    gemm_kernel<ND, NH, 1, 1><<<g1, 256>>>(nullptr,
        x[0],x[1],x[2],x[3],x[4],x[5],x[6],x[7], w_in, b_in, pY1);

    dim3 g2(32, NH/64, NE);
    gemm_kernel<NH, NH, 1, 0><<<g2, 256>>>(pY1,
        nullptr,nullptr,nullptr,nullptr,nullptr,nullptr,nullptr,nullptr, w_h, b_h, pY2);

    dim3 g3(32, NO/64, NE);
    gemm_kernel<NH, NO, 0, 0><<<g3, 256>>>(pY2,
        nullptr,nullptr,nullptr,nullptr,nullptr,nullptr,nullptr,nullptr, w_out, b_out, pY3);

    combine_kernel<<<dim3(NB, NO/256), 256>>>(out, pY3);
}

// round 3
// speedup vs baseline: 1.7594x; 1.7594x over previous
#include <cuda_runtime.h>
#include <cuda_bf16.h>
#include <cstdint>
#include <math.h>

#define NE 8
#define ND 1024
#define NH 2048
#define NO 1024
#define NB 4096
#define NSLOT (2*NB)

// ---------------- static device scratch ----------------
static __device__ __align__(256) __nv_bfloat16 g_Xhi[(size_t)NE*NB*ND];
static __device__ __align__(256) __nv_bfloat16 g_Xlo[(size_t)NE*NB*ND];
static __device__ __align__(256) __nv_bfloat16 g_W1hi[(size_t)NE*NH*ND];
static __device__ __align__(256) __nv_bfloat16 g_W1lo[(size_t)NE*NH*ND];
static __device__ __align__(256) __nv_bfloat16 g_W2hi[(size_t)NE*NH*NH];
static __device__ __align__(256) __nv_bfloat16 g_W2lo[(size_t)NE*NH*NH];
static __device__ __align__(256) __nv_bfloat16 g_W3hi[(size_t)NE*NO*NH];
static __device__ __align__(256) __nv_bfloat16 g_W3lo[(size_t)NE*NO*NH];
static __device__ __align__(256) __nv_bfloat16 g_Y1hi[(size_t)NSLOT*NH];
static __device__ __align__(256) __nv_bfloat16 g_Y1lo[(size_t)NSLOT*NH];
static __device__ __align__(256) __nv_bfloat16 g_Y2hi[(size_t)NSLOT*NH];
static __device__ __align__(256) __nv_bfloat16 g_Y2lo[(size_t)NSLOT*NH];
static __device__ __align__(256) float         g_Y3[(size_t)NSLOT*NO];
static __device__ int   g_gidx[NB * 2];
static __device__ float g_gwt[NB * 2];
static __device__ int   g_slot[NB * 2];
static __device__ int   g_cnt[NE];
static __device__ int   g_off[NE];
static __device__ int   g_cur[NE];
static __device__ int   g_rowtok[NSLOT];

// ---------------- PTX helpers (compute_103-safe: sm_80-era ops only) ----------
__device__ __forceinline__ uint32_t smem_u32(const void* p) {
    uint32_t a;
    asm("{ .reg .u64 t; cvta.to.shared.u64 t, %1; cvt.u32.u64 %0, t; }" : "=r"(a) : "l"(p));
    return a;
}
__device__ __forceinline__ void cp16(uint32_t s, const void* g) {
    asm volatile("cp.async.cg.shared.global [%0], [%1], 16;" :: "r"(s), "l"(g));
}
__device__ __forceinline__ void cp_commit() {
    asm volatile("cp.async.commit_group;" ::: "memory");
}
template<int N>
__device__ __forceinline__ void cp_wait() {
    asm volatile("cp.async.wait_group %0;" :: "n"(N) : "memory");
}
__device__ __forceinline__ void ldsm4(uint32_t& r0, uint32_t& r1, uint32_t& r2, uint32_t& r3,
                                      uint32_t addr) {
    asm volatile("ldmatrix.sync.aligned.m8n8.x4.shared.b16 {%0,%1,%2,%3}, [%4];"
                 : "=r"(r0), "=r"(r1), "=r"(r2), "=r"(r3) : "r"(addr));
}
__device__ __forceinline__ void mma16816(float* d, const uint32_t* a, uint32_t b0, uint32_t b1) {
    asm volatile("mma.sync.aligned.m16n8k16.row.col.f32.bf16.bf16.f32 "
                 "{%0,%1,%2,%3}, {%4,%5,%6,%7}, {%8,%9}, {%0,%1,%2,%3};"
                 : "+f"(d[0]), "+f"(d[1]), "+f"(d[2]), "+f"(d[3])
                 : "r"(a[0]), "r"(a[1]), "r"(a[2]), "r"(a[3]), "r"(b0), "r"(b1));
}

// ---------------- prep: split x into bf16 hi/lo ----------------
__global__ void prep_x_kernel(const float* __restrict__ x0, const float* __restrict__ x1,
                              const float* __restrict__ x2, const float* __restrict__ x3,
                              const float* __restrict__ x4, const float* __restrict__ x5,
                              const float* __restrict__ x6, const float* __restrict__ x7,
                              __nv_bfloat16* __restrict__ Xhi, __nv_bfloat16* __restrict__ Xlo)
{
    const float* xs[NE] = {x0,x1,x2,x3,x4,x5,x6,x7};
    int e = blockIdx.y;
    size_t i = (size_t)blockIdx.x * 256 + threadIdx.x;   // float4 index
    float4 v = ((const float4*)xs[e])[i];
    size_t o = (size_t)e * NB * ND + i * 4;
    __nv_bfloat16 h0 = __float2bfloat16(v.x), h1 = __float2bfloat16(v.y);
    __nv_bfloat16 h2 = __float2bfloat16(v.z), h3 = __float2bfloat16(v.w);
    __nv_bfloat16 l0 = __float2bfloat16(v.x - __bfloat162float(h0));
    __nv_bfloat16 l1 = __float2bfloat16(v.y - __bfloat162float(h1));
    __nv_bfloat16 l2 = __float2bfloat16(v.z - __bfloat162float(h2));
    __nv_bfloat16 l3 = __float2bfloat16(v.w - __bfloat162float(h3));
    *(__nv_bfloat162*)(Xhi + o)     = __halves2bfloat162(h0, h1);
    *(__nv_bfloat162*)(Xhi + o + 2) = __halves2bfloat162(h2, h3);
    *(__nv_bfloat162*)(Xlo + o)     = __halves2bfloat162(l0, l1);
    *(__nv_bfloat162*)(Xlo + o + 2) = __halves2bfloat162(l2, l3);
}

// ---------------- prep: transpose+split W[K,N] -> WT[N,K] hi/lo ----------------
template<int K, int N>
__global__ void prep_w_kernel(const float* __restrict__ W,
                              __nv_bfloat16* __restrict__ Thi, __nv_bfloat16* __restrict__ Tlo)
{
    __shared__ float t[32][33];
    int e = blockIdx.z;
    int k0 = blockIdx.x * 32, n0 = blockIdx.y * 32;
    int tx = threadIdx.x, ty = threadIdx.y;
    const float* Wp = W + (size_t)e * K * N;
#pragma unroll
    for (int j = 0; j < 4; j++)
        t[ty + 8*j][tx] = Wp[(size_t)(k0 + ty + 8*j) * N + n0 + tx];
    __syncthreads();
#pragma unroll
    for (int j = 0; j < 4; j++) {
        int nl = ty + 8*j;
        float v = t[tx][nl];
        __nv_bfloat16 h = __float2bfloat16(v);
        __nv_bfloat16 lo = __float2bfloat16(v - __bfloat162float(h));
        size_t o = ((size_t)e * N + n0 + nl) * K + k0 + tx;
        Thi[o] = h; Tlo[o] = lo;
    }
}

// ---------------- gating ----------------
__global__ void gate_kernel(const float* __restrict__ x0, const float* __restrict__ x1,
                            const float* __restrict__ x2, const float* __restrict__ x3,
                            const float* __restrict__ x4, const float* __restrict__ x5,
                            const float* __restrict__ x6, const float* __restrict__ x7,
                            const float* __restrict__ gw, const float* __restrict__ gb)
{
    int b   = blockIdx.x;
    int tid = threadIdx.x;
    const float* xs[NE] = {x0,x1,x2,x3,x4,x5,x6,x7};

    float acc[NE];
#pragma unroll
    for (int e = 0; e < NE; e++) acc[e] = 0.f;

#pragma unroll
    for (int ix = 0; ix < NE; ix++) {
        const float* xp = xs[ix] + (size_t)b * ND;
        for (int d = tid; d < ND; d += 256) {
            float v = xp[d];
            const float* g = gw + (size_t)(ix * ND + d) * NE;
#pragma unroll
            for (int e = 0; e < NE; e++) acc[e] += v * g[e];
        }
    }

    __shared__ float red[NE][256];
#pragma unroll
    for (int e = 0; e < NE; e++) red[e][tid] = acc[e];
    __syncthreads();
    for (int off = 128; off > 0; off >>= 1) {
        if (tid < off) {
#pragma unroll
            for (int e = 0; e < NE; e++) red[e][tid] += red[e][tid + off];
        }
        __syncthreads();
    }

    if (tid == 0) {
        float lg[NE];
#pragma unroll
        for (int e = 0; e < NE; e++) lg[e] = red[e][0] + gb[e];
        int i0 = 0;
#pragma unroll
        for (int e = 1; e < NE; e++) if (lg[e] > lg[i0]) i0 = e;
        int i1 = (i0 == 0) ? 1 : 0;
#pragma unroll
        for (int e = 0; e < NE; e++) if (e != i0 && lg[e] > lg[i1]) i1 = e;
        float ex = expf(lg[i1] - lg[i0]);
        float inv = 1.f / (1.f + ex);
        g_gidx[2*b]   = i0;  g_gidx[2*b+1] = i1;
        g_gwt[2*b]    = inv; g_gwt[2*b+1]  = ex * inv;
    }
}

// ---------------- dispatch bookkeeping ----------------
__global__ void init_cnt_kernel() { if (threadIdx.x < NE) g_cnt[threadIdx.x] = 0; }

__global__ void count_kernel() {
    int b = blockIdx.x * blockDim.x + threadIdx.x;
    if (b < NB) {
        atomicAdd(&g_cnt[g_gidx[2*b]],   1);
        atomicAdd(&g_cnt[g_gidx[2*b+1]], 1);
    }
}

__global__ void offs_kernel() {
    if (threadIdx.x == 0) {
        int s = 0;
        for (int e = 0; e < NE; e++) { g_off[e] = s; g_cur[e] = s; s += g_cnt[e]; }
    }
}

__global__ void scatter_kernel() {
    int b = blockIdx.x * blockDim.x + threadIdx.x;
    if (b < NB) {
#pragma unroll
        for (int k = 0; k < 2; k++) {
            int e = g_gidx[2*b + k];
            int p = atomicAdd(&g_cur[e], 1);
            g_rowtok[p]   = b;
            g_slot[2*b+k] = p;
        }
    }
}

// ---------------- mma.sync split-bf16 GEMM ----------------
// CTA tile 128x128, BK=64 (128B rows, XOR-swizzled smem, SW128 pattern).
// 8 warps: warp (wm 0..3, wn 0..1) computes 32x64.
// 3 mma terms per k16-step: AhBh + AhBl + AlBh into fp32 accum.
static constexpr int SMEM_STAGE = 65536;   // Ahi/Alo/Whi/Wlo 16KB each
static constexpr int SMEM_SZ = 1024 + 2 * SMEM_STAGE;

template<int K, int NTOT, int OUTSPLIT, int GATHER>
__global__ __launch_bounds__(256, 1)
void moe_gemm(const __nv_bfloat16* __restrict__ Ahi, const __nv_bfloat16* __restrict__ Alo,
              const __nv_bfloat16* __restrict__ Whi, const __nv_bfloat16* __restrict__ Wlo,
              const float* __restrict__ Bg,
              __nv_bfloat16* __restrict__ Chi, __nv_bfloat16* __restrict__ Clo,
              float* __restrict__ Cf)
{
    constexpr int NCH = K / 64;
    int e   = blockIdx.z;
    int cnt = g_cnt[e];
    int m0  = blockIdx.x * 128;
    if (m0 >= cnt) return;
    int base = g_off[e];
    int n0   = blockIdx.y * 128;
    int tid  = threadIdx.x;

    extern __shared__ __align__(1024) char smem[];
    float* sBias = (float*)smem;                   // [0,512)
    uint32_t smBase = smem_u32(smem) + 1024;       // stages

    if (tid < 128) sBias[tid] = Bg[(size_t)e * NTOT + n0 + tid];

    // ---- loader mapping: row r = tid>>1 (0..127), chunks (tid&1)*4 + 0..3 ----
    int r     = tid >> 1;
    int cbase = (tid & 1) * 4;
    uint32_t rowOff = (uint32_t)(r * 128);
    int r7 = r & 7;

    size_t aO;   // element offset of this thread's A row
    {
        int m  = m0 + r;
        int mc = (m < cnt) ? m : 0;
        if (GATHER) aO = ((size_t)e * NB + g_rowtok[base + mc]) * K;
        else        aO = (size_t)(base + mc) * K;
    }
    size_t wO = ((size_t)e * NTOT + n0 + r) * K;

    auto loadChunk = [&](int k0el, int p) {
        uint32_t st = smBase + p * SMEM_STAGE;
        const __nv_bfloat16* pAh = Ahi + aO + k0el;
        const __nv_bfloat16* pAl = Alo + aO + k0el;
        const __nv_bfloat16* pWh = Whi + wO + k0el;
        const __nv_bfloat16* pWl = Wlo + wO + k0el;
#pragma unroll
        for (int j = 0; j < 4; j++) {
            int c = cbase + j;
            uint32_t soff = rowOff + (uint32_t)((c ^ r7) << 4);
            cp16(st +         soff, pAh + c * 8);
            cp16(st + 16384 + soff, pAl + c * 8);
            cp16(st + 32768 + soff, pWh + c * 8);
            cp16(st + 49152 + soff, pWl + c * 8);
        }
    };

    // ---- compute mapping ----
    int w    = tid >> 5;
    int lane = tid & 31;
    int wm = w >> 1;       // 0..3 -> 32-row band
    int wn = w & 1;        // 0..1 -> 64-col band
    int lr16 = lane & 15;
    int lcc  = lane >> 4;

    float acc[2][8][4];
#pragma unroll
    for (int a = 0; a < 2; a++)
#pragma unroll
        for (int b = 0; b < 8; b++)
#pragma unroll
            for (int c = 0; c < 4; c++) acc[a][b][c] = 0.f;

    loadChunk(0, 0);
    cp_commit();

    for (int ch = 0; ch < NCH; ch++) {
        if (ch + 1 < NCH) {
            loadChunk((ch + 1) * 64, (ch + 1) & 1);
            cp_commit();
            cp_wait<1>();
        } else {
            cp_wait<0>();
        }
        __syncthreads();

        uint32_t st = smBase + (ch & 1) * SMEM_STAGE;
#pragma unroll
        for (int ks = 0; ks < 4; ks++) {
            int cc = ks * 2 + lcc;
            uint32_t ah[2][4], al[2][4], bh[4][4], bl[4][4];
#pragma unroll
            for (int mi = 0; mi < 2; mi++) {
                int row = wm * 32 + mi * 16 + lr16;
                uint32_t off = (uint32_t)(row * 128 + ((cc ^ (row & 7)) << 4));
                ldsm4(ah[mi][0], ah[mi][1], ah[mi][2], ah[mi][3], st + off);
                ldsm4(al[mi][0], al[mi][1], al[mi][2], al[mi][3], st + 16384 + off);
            }
#pragma unroll
            for (int ni = 0; ni < 4; ni++) {
                int row = wn * 64 + ni * 16 + lr16;
                uint32_t off = (uint32_t)(row * 128 + ((cc ^ (row & 7)) << 4));
                ldsm4(bh[ni][0], bh[ni][1], bh[ni][2], bh[ni][3], st + 32768 + off);
                ldsm4(bl[ni][0], bl[ni][1], bl[ni][2], bl[ni][3], st + 49152 + off);
            }
#pragma unroll
            for (int mi = 0; mi < 2; mi++) {
#pragma unroll
                for (int ni = 0; ni < 4; ni++) {
                    // n8 tile 2*ni   : fragment (b[0], b[2])
                    mma16816(acc[mi][2*ni],     ah[mi], bh[ni][0], bh[ni][2]);
                    mma16816(acc[mi][2*ni],     ah[mi], bl[ni][0], bl[ni][2]);
                    mma16816(acc[mi][2*ni],     al[mi], bh[ni][0], bh[ni][2]);
                    // n8 tile 2*ni+1 : fragment (b[1], b[3])
                    mma16816(acc[mi][2*ni+1],   ah[mi], bh[ni][1], bh[ni][3]);
                    mma16816(acc[mi][2*ni+1],   ah[mi], bl[ni][1], bl[ni][3]);
                    mma16816(acc[mi][2*ni+1],   al[mi], bh[ni][1], bh[ni][3]);
                }
            }
        }
        __syncthreads();
    }

    // ---- epilogue ----
    int lr = lane >> 2;        // 0..7
    int lc = (lane & 3) * 2;   // 0,2,4,6
#pragma unroll
    for (int mi = 0; mi < 2; mi++) {
#pragma unroll
        for (int h = 0; h < 2; h++) {
            int m = m0 + wm * 32 + mi * 16 + lr + h * 8;
            if (m >= cnt) continue;
            size_t crow = (size_t)(base + m);
#pragma unroll
            for (int nj = 0; nj < 8; nj++) {
                int colLocal = wn * 64 + nj * 8 + lc;
                float v0 = acc[mi][nj][h * 2 + 0] + sBias[colLocal];
                float v1 = acc[mi][nj][h * 2 + 1] + sBias[colLocal + 1];
                if (OUTSPLIT) {
                    v0 = fmaxf(v0, 0.f);
                    v1 = fmaxf(v1, 0.f);
                    __nv_bfloat16 h0 = __float2bfloat16(v0), h1 = __float2bfloat16(v1);
                    __nv_bfloat16 l0 = __float2bfloat16(v0 - __bfloat162float(h0));
                    __nv_bfloat16 l1 = __float2bfloat16(v1 - __bfloat162float(h1));
                    *(__nv_bfloat162*)(Chi + crow * NTOT + n0 + colLocal) = __halves2bfloat162(h0, h1);
                    *(__nv_bfloat162*)(Clo + crow * NTOT + n0 + colLocal) = __halves2bfloat162(l0, l1);
                } else {
                    float2 v; v.x = v0; v.y = v1;
                    *(float2*)(Cf + crow * NTOT + n0 + colLocal) = v;
                }
            }
        }
    }
}

// ---------------- combine ----------------
__global__ void combine_kernel(float* __restrict__ out, const float* __restrict__ Y3)
{
    int b = blockIdx.x;
    int o = blockIdx.y * 256 + threadIdx.x;
    int s0 = g_slot[2*b], s1 = g_slot[2*b+1];
    float w0 = g_gwt[2*b], w1 = g_gwt[2*b+1];
    out[(size_t)b * NO + o] = w0 * Y3[(size_t)s0 * NO + o]
                            + w1 * Y3[(size_t)s1 * NO + o];
}

// ============================================================
extern "C" void kernel_launch(void* const* d_in, const int* in_sizes, int n_in,
                              void* d_out, int out_size)
{
    const float* x[NE];
    for (int i = 0; i < NE; i++) x[i] = (const float*)d_in[i];
    const float* gw    = (const float*)d_in[8];
    const float* gb    = (const float*)d_in[9];
    const float* w_in  = (const float*)d_in[10];
    const float* b_in  = (const float*)d_in[11];
    const float* w_h   = (const float*)d_in[12];
    const float* b_h   = (const float*)d_in[13];
    const float* w_out = (const float*)d_in[14];
    const float* b_out = (const float*)d_in[15];
    float* out = (float*)d_out;

    __nv_bfloat16 *pXhi, *pXlo, *pW1hi, *pW1lo, *pW2hi, *pW2lo, *pW3hi, *pW3lo;
    __nv_bfloat16 *pY1hi, *pY1lo, *pY2hi, *pY2lo;
    float* pY3;
    cudaGetSymbolAddress((void**)&pXhi,  g_Xhi);
    cudaGetSymbolAddress((void**)&pXlo,  g_Xlo);
    cudaGetSymbolAddress((void**)&pW1hi, g_W1hi);
    cudaGetSymbolAddress((void**)&pW1lo, g_W1lo);
    cudaGetSymbolAddress((void**)&pW2hi, g_W2hi);
    cudaGetSymbolAddress((void**)&pW2lo, g_W2lo);
    cudaGetSymbolAddress((void**)&pW3hi, g_W3hi);
    cudaGetSymbolAddress((void**)&pW3lo, g_W3lo);
    cudaGetSymbolAddress((void**)&pY1hi, g_Y1hi);
    cudaGetSymbolAddress((void**)&pY1lo, g_Y1lo);
    cudaGetSymbolAddress((void**)&pY2hi, g_Y2hi);
    cudaGetSymbolAddress((void**)&pY2lo, g_Y2lo);
    cudaGetSymbolAddress((void**)&pY3,   g_Y3);

    cudaFuncSetAttribute(moe_gemm<ND, NH, 1, 1>, cudaFuncAttributeMaxDynamicSharedMemorySize, SMEM_SZ);
    cudaFuncSetAttribute(moe_gemm<NH, NH, 1, 0>, cudaFuncAttributeMaxDynamicSharedMemorySize, SMEM_SZ);
    cudaFuncSetAttribute(moe_gemm<NH, NO, 0, 0>, cudaFuncAttributeMaxDynamicSharedMemorySize, SMEM_SZ);

    // prep passes
    prep_x_kernel<<<dim3(NB * ND / 4 / 256, NE), 256>>>(
        x[0],x[1],x[2],x[3],x[4],x[5],x[6],x[7], pXhi, pXlo);
    prep_w_kernel<ND, NH><<<dim3(ND/32, NH/32, NE), dim3(32, 8)>>>(w_in,  pW1hi, pW1lo);
    prep_w_kernel<NH, NH><<<dim3(NH/32, NH/32, NE), dim3(32, 8)>>>(w_h,   pW2hi, pW2lo);
    prep_w_kernel<NH, NO><<<dim3(NH/32, NO/32, NE), dim3(32, 8)>>>(w_out, pW3hi, pW3lo);

    // gating + dispatch
    gate_kernel<<<NB, 256>>>(x[0],x[1],x[2],x[3],x[4],x[5],x[6],x[7], gw, gb);
    init_cnt_kernel<<<1, 32>>>();
    count_kernel<<<NB/256, 256>>>();
    offs_kernel<<<1, 32>>>();
    scatter_kernel<<<NB/256, 256>>>();

    // expert GEMMs (mma.sync, split-bf16)
    moe_gemm<ND, NH, 1, 1><<<dim3(32, NH/128, NE), 256, SMEM_SZ>>>(
        pXhi, pXlo, pW1hi, pW1lo, b_in, pY1hi, pY1lo, nullptr);
    moe_gemm<NH, NH, 1, 0><<<dim3(32, NH/128, NE), 256, SMEM_SZ>>>(
        pY1hi, pY1lo, pW2hi, pW2lo, b_h, pY2hi, pY2lo, nullptr);
    moe_gemm<NH, NO, 0, 0><<<dim3(32, NO/128, NE), 256, SMEM_SZ>>>(
        pY2hi, pY2lo, pW3hi, pW3lo, b_out, nullptr, nullptr, pY3);

    combine_kernel<<<dim3(NB, NO/256), 256>>>(out, pY3);
}

// round 4
// speedup vs baseline: 2.8101x; 1.5972x over previous
#include <cuda_runtime.h>
#include <cuda_fp16.h>
#include <cstdint>
#include <math.h>

#define NE 8
#define ND 1024
#define NH 2048
#define NO 1024
#define NB 4096
#define NSLOT (2*NB)

// ---------------- static device scratch ----------------
static __device__ __align__(256) __half g_Xhi[(size_t)NE*NB*ND];
static __device__ __align__(256) __half g_Xlo[(size_t)NE*NB*ND];
static __device__ __align__(256) __half g_W1hi[(size_t)NE*NH*ND];
static __device__ __align__(256) __half g_W2hi[(size_t)NE*NH*NH];
static __device__ __align__(256) __half g_W3hi[(size_t)NE*NO*NH];
static __device__ __align__(256) __half g_Y1hi[(size_t)NSLOT*NH];
static __device__ __align__(256) __half g_Y1lo[(size_t)NSLOT*NH];
static __device__ __align__(256) __half g_Y2hi[(size_t)NSLOT*NH];
static __device__ __align__(256) __half g_Y2lo[(size_t)NSLOT*NH];
static __device__ __align__(256) float  g_Y3[(size_t)NSLOT*NO];
static __device__ int   g_gidx[NB * 2];
static __device__ float g_gwt[NB * 2];
static __device__ int   g_slot[NB * 2];
static __device__ int   g_cnt[NE];
static __device__ int   g_off[NE];
static __device__ int   g_cur[NE];
static __device__ int   g_rowtok[NSLOT];

// ---------------- PTX helpers (compute_103-safe, sm_80-era) ----------------
__device__ __forceinline__ uint32_t smem_u32(const void* p) {
    uint32_t a;
    asm("{ .reg .u64 t; cvta.to.shared.u64 t, %1; cvt.u32.u64 %0, t; }" : "=r"(a) : "l"(p));
    return a;
}
__device__ __forceinline__ void cp16(uint32_t s, const void* g) {
    asm volatile("cp.async.cg.shared.global [%0], [%1], 16;" :: "r"(s), "l"(g));
}
__device__ __forceinline__ void cp_commit() {
    asm volatile("cp.async.commit_group;" ::: "memory");
}
template<int N>
__device__ __forceinline__ void cp_wait() {
    asm volatile("cp.async.wait_group %0;" :: "n"(N) : "memory");
}
__device__ __forceinline__ void ldsm4(uint32_t& r0, uint32_t& r1, uint32_t& r2, uint32_t& r3,
                                      uint32_t addr) {
    asm volatile("ldmatrix.sync.aligned.m8n8.x4.shared.b16 {%0,%1,%2,%3}, [%4];"
                 : "=r"(r0), "=r"(r1), "=r"(r2), "=r"(r3) : "r"(addr));
}
__device__ __forceinline__ void mma16816(float* d, const uint32_t* a, uint32_t b0, uint32_t b1) {
    asm volatile("mma.sync.aligned.m16n8k16.row.col.f32.f16.f16.f32 "
                 "{%0,%1,%2,%3}, {%4,%5,%6,%7}, {%8,%9}, {%0,%1,%2,%3};"
                 : "+f"(d[0]), "+f"(d[1]), "+f"(d[2]), "+f"(d[3])
                 : "r"(a[0]), "r"(a[1]), "r"(a[2]), "r"(a[3]), "r"(b0), "r"(b1));
}

// ---------------- prep: split x into fp16 hi/lo (22-bit exact) ----------------
__global__ void prep_x_kernel(const float* __restrict__ x0, const float* __restrict__ x1,
                              const float* __restrict__ x2, const float* __restrict__ x3,
                              const float* __restrict__ x4, const float* __restrict__ x5,
                              const float* __restrict__ x6, const float* __restrict__ x7,
                              __half* __restrict__ Xhi, __half* __restrict__ Xlo)
{
    const float* xs[NE] = {x0,x1,x2,x3,x4,x5,x6,x7};
    int e = blockIdx.y;
    size_t i = (size_t)blockIdx.x * 256 + threadIdx.x;   // float4 index
    float4 v = ((const float4*)xs[e])[i];
    size_t o = (size_t)e * NB * ND + i * 4;
    __half h0 = __float2half(v.x), h1 = __float2half(v.y);
    __half h2 = __float2half(v.z), h3 = __float2half(v.w);
    __half l0 = __float2half(v.x - __half2float(h0));
    __half l1 = __float2half(v.y - __half2float(h1));
    __half l2 = __float2half(v.z - __half2float(h2));
    __half l3 = __float2half(v.w - __half2float(h3));
    *(__half2*)(Xhi + o)     = __halves2half2(h0, h1);
    *(__half2*)(Xhi + o + 2) = __halves2half2(h2, h3);
    *(__half2*)(Xlo + o)     = __halves2half2(l0, l1);
    *(__half2*)(Xlo + o + 2) = __halves2half2(l2, l3);
}

// ---------------- prep: transpose W[K,N] -> WT[N,K] fp16 ----------------
template<int K, int N>
__global__ void prep_w_kernel(const float* __restrict__ W, __half* __restrict__ Thi)
{
    __shared__ float t[32][33];
    int e = blockIdx.z;
    int k0 = blockIdx.x * 32, n0 = blockIdx.y * 32;
    int tx = threadIdx.x, ty = threadIdx.y;
    const float* Wp = W + (size_t)e * K * N;
#pragma unroll
    for (int j = 0; j < 4; j++)
        t[ty + 8*j][tx] = Wp[(size_t)(k0 + ty + 8*j) * N + n0 + tx];
    __syncthreads();
#pragma unroll
    for (int j = 0; j < 4; j++) {
        int nl = ty + 8*j;
        size_t o = ((size_t)e * N + n0 + nl) * K + k0 + tx;
        Thi[o] = __float2half(t[tx][nl]);
    }
}

// ---------------- gating ----------------
__global__ void gate_kernel(const float* __restrict__ x0, const float* __restrict__ x1,
                            const float* __restrict__ x2, const float* __restrict__ x3,
                            const float* __restrict__ x4, const float* __restrict__ x5,
                            const float* __restrict__ x6, const float* __restrict__ x7,
                            const float* __restrict__ gw, const float* __restrict__ gb)
{
    int b   = blockIdx.x;
    int tid = threadIdx.x;
    const float* xs[NE] = {x0,x1,x2,x3,x4,x5,x6,x7};

    float acc[NE];
#pragma unroll
    for (int e = 0; e < NE; e++) acc[e] = 0.f;

#pragma unroll
    for (int ix = 0; ix < NE; ix++) {
        const float* xp = xs[ix] + (size_t)b * ND;
        for (int d = tid; d < ND; d += 256) {
            float v = xp[d];
            const float* g = gw + (size_t)(ix * ND + d) * NE;
#pragma unroll
            for (int e = 0; e < NE; e++) acc[e] += v * g[e];
        }
    }

    __shared__ float red[NE][256];
#pragma unroll
    for (int e = 0; e < NE; e++) red[e][tid] = acc[e];
    __syncthreads();
    for (int off = 128; off > 0; off >>= 1) {
        if (tid < off) {
#pragma unroll
            for (int e = 0; e < NE; e++) red[e][tid] += red[e][tid + off];
        }
        __syncthreads();
    }

    if (tid == 0) {
        float lg[NE];
#pragma unroll
        for (int e = 0; e < NE; e++) lg[e] = red[e][0] + gb[e];
        int i0 = 0;
#pragma unroll
        for (int e = 1; e < NE; e++) if (lg[e] > lg[i0]) i0 = e;
        int i1 = (i0 == 0) ? 1 : 0;
#pragma unroll
        for (int e = 0; e < NE; e++) if (e != i0 && lg[e] > lg[i1]) i1 = e;
        float ex = expf(lg[i1] - lg[i0]);
        float inv = 1.f / (1.f + ex);
        g_gidx[2*b]   = i0;  g_gidx[2*b+1] = i1;
        g_gwt[2*b]    = inv; g_gwt[2*b+1]  = ex * inv;
    }
}

// ---------------- dispatch bookkeeping ----------------
__global__ void init_cnt_kernel() { if (threadIdx.x < NE) g_cnt[threadIdx.x] = 0; }

__global__ void count_kernel() {
    int b = blockIdx.x * blockDim.x + threadIdx.x;
    if (b < NB) {
        atomicAdd(&g_cnt[g_gidx[2*b]],   1);
        atomicAdd(&g_cnt[g_gidx[2*b+1]], 1);
    }
}

__global__ void offs_kernel() {
    if (threadIdx.x == 0) {
        int s = 0;
        for (int e = 0; e < NE; e++) { g_off[e] = s; g_cur[e] = s; s += g_cnt[e]; }
    }
}

__global__ void scatter_kernel() {
    int b = blockIdx.x * blockDim.x + threadIdx.x;
    if (b < NB) {
#pragma unroll
        for (int k = 0; k < 2; k++) {
            int e = g_gidx[2*b + k];
            int p = atomicAdd(&g_cur[e], 1);
            g_rowtok[p]   = b;
            g_slot[2*b+k] = p;
        }
    }
}

// ---------------- mma.sync fp16 2-term GEMM ----------------
// CTA tile 128x256, BK=32. 512 threads = 16 warps, warp tile 32x64.
// Terms: Ah*Bh + Al*Bh into fp32 accum. 3-stage cp.async pipeline.
// Smem rows = 64B; swizzle chunk ^= (row>>1)&3 -> conflict-free ldmatrix.
static constexpr int SMEM_STAGE = 32768;   // Ah 8K + Al 8K + Bh 16K
static constexpr int SMEM_SZ = 1024 + 3 * SMEM_STAGE;

template<int K, int NTOT, int OUTSPLIT, int GATHER>
__global__ __launch_bounds__(512, 1)
void moe_gemm(const __half* __restrict__ Ahi, const __half* __restrict__ Alo,
              const __half* __restrict__ Whi,
              const float* __restrict__ Bg,
              __half* __restrict__ Chi, __half* __restrict__ Clo,
              float* __restrict__ Cf)
{
    constexpr int NCH = K / 32;
    int e   = blockIdx.z;
    int cnt = g_cnt[e];
    int m0  = blockIdx.x * 128;
    if (m0 >= cnt) return;
    int base = g_off[e];
    int n0   = blockIdx.y * 256;
    int tid  = threadIdx.x;

    extern __shared__ __align__(1024) char smem[];
    float* sBias = (float*)smem;                   // [0,1024)
    uint32_t smBase = smem_u32(smem) + 1024;

    if (tid < 256) sBias[tid] = Bg[(size_t)e * NTOT + n0 + tid];

    // ---- loader mapping: row r = tid>>2 (0..127), chunk c = tid&3 ----
    int r = tid >> 2;
    int c = tid & 3;
    uint32_t sA = (uint32_t)(r * 64 + ((c ^ ((r >> 1) & 3)) << 4));

    size_t aO;
    {
        int m  = m0 + r;
        int mc = (m < cnt) ? m : 0;
        if (GATHER) aO = ((size_t)e * NB + g_rowtok[base + mc]) * K;
        else        aO = (size_t)(base + mc) * K;
    }
    size_t wO0 = ((size_t)e * NTOT + n0 + r) * K;
    size_t wO1 = wO0 + (size_t)128 * K;

    auto loadChunk = [&](int k0el, int slot) {
        uint32_t st = smBase + slot * SMEM_STAGE;
        cp16(st +          sA, Ahi + aO  + k0el + c * 8);
        cp16(st +  8192 + sA, Alo + aO  + k0el + c * 8);
        cp16(st + 16384 + sA, Whi + wO0 + k0el + c * 8);
        cp16(st + 24576 + sA, Whi + wO1 + k0el + c * 8);
    };

    // ---- compute mapping: 16 warps = 4(m) x 4(n), warp tile 32x64 ----
    int w    = tid >> 5;
    int lane = tid & 31;
    int wm = w >> 2;       // 0..3
    int wn = w & 3;        // 0..3
    int lr16 = lane & 15;
    int lcc  = lane >> 4;

    float acc[2][8][4];
#pragma unroll
    for (int a = 0; a < 2; a++)
#pragma unroll
        for (int b = 0; b < 8; b++)
#pragma unroll
            for (int d = 0; d < 4; d++) acc[a][b][d] = 0.f;

    loadChunk(0, 0);  cp_commit();
    loadChunk(32, 1); cp_commit();

    int cur = 0, nxt = 2;
    for (int ch = 0; ch < NCH; ch++) {
        if (ch + 1 < NCH) cp_wait<1>(); else cp_wait<0>();
        __syncthreads();
        if (ch + 2 < NCH) {
            loadChunk((ch + 2) * 32, nxt);
            cp_commit();
        }

        uint32_t st = smBase + cur * SMEM_STAGE;
#pragma unroll
        for (int ks = 0; ks < 2; ks++) {
            int cc = ks * 2 + lcc;
            uint32_t ah[2][4], al[2][4];
#pragma unroll
            for (int mi = 0; mi < 2; mi++) {
                int row = wm * 32 + mi * 16 + lr16;
                uint32_t off = (uint32_t)(row * 64 + ((cc ^ ((row >> 1) & 3)) << 4));
                ldsm4(ah[mi][0], ah[mi][1], ah[mi][2], ah[mi][3], st + off);
                ldsm4(al[mi][0], al[mi][1], al[mi][2], al[mi][3], st + 8192 + off);
            }
#pragma unroll
            for (int ni = 0; ni < 4; ni++) {
                int row = wn * 64 + ni * 16 + lr16;
                uint32_t off = (uint32_t)(row * 64 + ((cc ^ ((row >> 1) & 3)) << 4));
                uint32_t b0, b1, b2, b3;
                ldsm4(b0, b1, b2, b3, st + 16384 + off);
#pragma unroll
                for (int mi = 0; mi < 2; mi++) {
                    mma16816(acc[mi][2*ni],   ah[mi], b0, b2);
                    mma16816(acc[mi][2*ni],   al[mi], b0, b2);
                    mma16816(acc[mi][2*ni+1], ah[mi], b1, b3);
                    mma16816(acc[mi][2*ni+1], al[mi], b1, b3);
                }
            }
        }
        cur = (cur == 2) ? 0 : cur + 1;
        nxt = (nxt == 2) ? 0 : nxt + 1;
    }

    // ---- epilogue ----
    int lr = lane >> 2;        // 0..7
    int lc = (lane & 3) * 2;   // 0,2,4,6
#pragma unroll
    for (int mi = 0; mi < 2; mi++) {
#pragma unroll
        for (int h = 0; h < 2; h++) {
            int m = m0 + wm * 32 + mi * 16 + lr + h * 8;
            if (m >= cnt) continue;
            size_t crow = (size_t)(base + m);
#pragma unroll
            for (int nj = 0; nj < 8; nj++) {
                int colLocal = wn * 64 + nj * 8 + lc;
                float v0 = acc[mi][nj][h * 2 + 0] + sBias[colLocal];
                float v1 = acc[mi][nj][h * 2 + 1] + sBias[colLocal + 1];
                if (OUTSPLIT) {
                    v0 = fmaxf(v0, 0.f);
                    v1 = fmaxf(v1, 0.f);
                    __half h0 = __float2half(v0), h1 = __float2half(v1);
                    __half l0 = __float2half(v0 - __half2float(h0));
                    __half l1 = __float2half(v1 - __half2float(h1));
                    *(__half2*)(Chi + crow * NTOT + n0 + colLocal) = __halves2half2(h0, h1);
                    *(__half2*)(Clo + crow * NTOT + n0 + colLocal) = __halves2half2(l0, l1);
                } else {
                    float2 v; v.x = v0; v.y = v1;
                    *(float2*)(Cf + crow * NTOT + n0 + colLocal) = v;
                }
            }
        }
    }
}

// ---------------- combine ----------------
__global__ void combine_kernel(float* __restrict__ out, const float* __restrict__ Y3)
{
    int b = blockIdx.x;
    int o = blockIdx.y * 256 + threadIdx.x;
    int s0 = g_slot[2*b], s1 = g_slot[2*b+1];
    float w0 = g_gwt[2*b], w1 = g_gwt[2*b+1];
    out[(size_t)b * NO + o] = w0 * Y3[(size_t)s0 * NO + o]
                            + w1 * Y3[(size_t)s1 * NO + o];
}

// ============================================================
extern "C" void kernel_launch(void* const* d_in, const int* in_sizes, int n_in,
                              void* d_out, int out_size)
{
    const float* x[NE];
    for (int i = 0; i < NE; i++) x[i] = (const float*)d_in[i];
    const float* gw    = (const float*)d_in[8];
    const float* gb    = (const float*)d_in[9];
    const float* w_in  = (const float*)d_in[10];
    const float* b_in  = (const float*)d_in[11];
    const float* w_h   = (const float*)d_in[12];
    const float* b_h   = (const float*)d_in[13];
    const float* w_out = (const float*)d_in[14];
    const float* b_out = (const float*)d_in[15];
    float* out = (float*)d_out;

    __half *pXhi, *pXlo, *pW1hi, *pW2hi, *pW3hi;
    __half *pY1hi, *pY1lo, *pY2hi, *pY2lo;
    float* pY3;
    cudaGetSymbolAddress((void**)&pXhi,  g_Xhi);
    cudaGetSymbolAddress((void**)&pXlo,  g_Xlo);
    cudaGetSymbolAddress((void**)&pW1hi, g_W1hi);
    cudaGetSymbolAddress((void**)&pW2hi, g_W2hi);
    cudaGetSymbolAddress((void**)&pW3hi, g_W3hi);
    cudaGetSymbolAddress((void**)&pY1hi, g_Y1hi);
    cudaGetSymbolAddress((void**)&pY1lo, g_Y1lo);
    cudaGetSymbolAddress((void**)&pY2hi, g_Y2hi);
    cudaGetSymbolAddress((void**)&pY2lo, g_Y2lo);
    cudaGetSymbolAddress((void**)&pY3,   g_Y3);

    cudaFuncSetAttribute(moe_gemm<ND, NH, 1, 1>, cudaFuncAttributeMaxDynamicSharedMemorySize, SMEM_SZ);
    cudaFuncSetAttribute(moe_gemm<NH, NH, 1, 0>, cudaFuncAttributeMaxDynamicSharedMemorySize, SMEM_SZ);
    cudaFuncSetAttribute(moe_gemm<NH, NO, 0, 0>, cudaFuncAttributeMaxDynamicSharedMemorySize, SMEM_SZ);

    // prep passes
    prep_x_kernel<<<dim3(NB * ND / 4 / 256, NE), 256>>>(
        x[0],x[1],x[2],x[3],x[4],x[5],x[6],x[7], pXhi, pXlo);
    prep_w_kernel<ND, NH><<<dim3(ND/32, NH/32, NE), dim3(32, 8)>>>(w_in,  pW1hi);
    prep_w_kernel<NH, NH><<<dim3(NH/32, NH/32, NE), dim3(32, 8)>>>(w_h,   pW2hi);
    prep_w_kernel<NH, NO><<<dim3(NH/32, NO/32, NE), dim3(32, 8)>>>(w_out, pW3hi);

    // gating + dispatch
    gate_kernel<<<NB, 256>>>(x[0],x[1],x[2],x[3],x[4],x[5],x[6],x[7], gw, gb);
    init_cnt_kernel<<<1, 32>>>();
    count_kernel<<<NB/256, 256>>>();
    offs_kernel<<<1, 32>>>();
    scatter_kernel<<<NB/256, 256>>>();

    // expert GEMMs (mma.sync fp16, 2-term exact-A split)
    moe_gemm<ND, NH, 1, 1><<<dim3(32, NH/256, NE), 512, SMEM_SZ>>>(
        pXhi, pXlo, pW1hi, b_in, pY1hi, pY1lo, nullptr);
    moe_gemm<NH, NH, 1, 0><<<dim3(32, NH/256, NE), 512, SMEM_SZ>>>(
        pY1hi, pY1lo, pW2hi, b_h, pY2hi, pY2lo, nullptr);
    moe_gemm<NH, NO, 0, 0><<<dim3(32, NO/256, NE), 512, SMEM_SZ>>>(
        pY2hi, pY2lo, pW3hi, b_out, nullptr, nullptr, pY3);

    combine_kernel<<<dim3(NB, NO/256), 256>>>(out, pY3);
}